// round 10
// baseline (speedup 1.0000x reference)
#include <cuda_runtime.h>
#include <math.h>

#define N_BINS 1024
#define N_COPIES 8           // one PRIVATE smem histogram per warp (256 thr / 32)
#define HIST_BLOCKS 592      // 4 * 148 SMs (R3 best-known config)
#define HIST_THREADS 256

// bin pairs packed: g_counts64[b2] = (count[2*b2+1] << 32) | count[2*b2]
__device__ unsigned long long g_counts64[N_BINS / 2];  // zero at load; reset each run
__device__ unsigned int g_done;                        // arrival counter, reset each run

__global__ void __launch_bounds__(HIST_THREADS) hist_kernel(
    const int* __restrict__ idx, long long n, float inv_n,
    float* __restrict__ out)
{
    __shared__ __align__(16) unsigned int sh[N_COPIES][N_BINS];
    __shared__ bool s_last;
    __shared__ float red[HIST_THREADS / 32];

    unsigned int* flat = &sh[0][0];
    for (int i = threadIdx.x; i < N_COPIES * N_BINS; i += blockDim.x)
        flat[i] = 0u;
    __syncthreads();

    unsigned int* h = sh[threadIdx.x >> 5];   // fully private per-warp copy

    long long tid    = (long long)blockIdx.x * blockDim.x + threadIdx.x;
    long long stride = (long long)gridDim.x * blockDim.x;
    long long n4     = n >> 2;
    const int4* p4   = (const int4*)idx;

    // main loop: 2 outstanding int4 loads per iteration (R3's exact body)
    long long i = tid;
    for (; i + stride < n4; i += 2 * stride) {
        int4 a = p4[i];
        int4 b = p4[i + stride];
        atomicAdd(&h[a.x & (N_BINS - 1)], 1u);
        atomicAdd(&h[a.y & (N_BINS - 1)], 1u);
        atomicAdd(&h[a.z & (N_BINS - 1)], 1u);
        atomicAdd(&h[a.w & (N_BINS - 1)], 1u);
        atomicAdd(&h[b.x & (N_BINS - 1)], 1u);
        atomicAdd(&h[b.y & (N_BINS - 1)], 1u);
        atomicAdd(&h[b.z & (N_BINS - 1)], 1u);
        atomicAdd(&h[b.w & (N_BINS - 1)], 1u);
    }
    for (; i < n4; i += stride) {
        int4 a = p4[i];
        atomicAdd(&h[a.x & (N_BINS - 1)], 1u);
        atomicAdd(&h[a.y & (N_BINS - 1)], 1u);
        atomicAdd(&h[a.z & (N_BINS - 1)], 1u);
        atomicAdd(&h[a.w & (N_BINS - 1)], 1u);
    }
    // remainder (n not multiple of 4)
    for (long long r = (n4 << 2) + tid; r < n; r += stride)
        atomicAdd(&h[idx[r] & (N_BINS - 1)], 1u);

    __syncthreads();

    // flush: sum 8 copies per bin pair, ONE 64-bit REDG per pair per block.
    // Per-block field <= n/HIST_BLOCKS < 2^16*? (57K) and global field <= n < 2^32:
    // no carry between the packed 32-bit halves.
    for (int b2 = threadIdx.x; b2 < N_BINS / 2; b2 += blockDim.x) {
        unsigned int lo = 0, hi = 0;
        #pragma unroll
        for (int c = 0; c < N_COPIES; c++) {
            uint2 q = *(const uint2*)&sh[c][2 * b2];
            lo += q.x; hi += q.y;
        }
        atomicAdd(&g_counts64[b2], ((unsigned long long)hi << 32) | lo);
    }

    // last-block-done: fused finalize
    __threadfence();
    if (threadIdx.x == 0)
        s_last = (atomicAdd(&g_done, 1u) == (unsigned)(gridDim.x - 1));
    __syncthreads();

    if (s_last) {
        int t = threadIdx.x;
        volatile unsigned long long* gc = g_counts64;
        float v = 0.0f;
        #pragma unroll
        for (int k = 0; k < (N_BINS / 2) / HIST_THREADS; k++) {
            int b2 = t + k * HIST_THREADS;
            unsigned long long c = gc[b2];
            g_counts64[b2] = 0ull;            // reset for next replay
            float p0 = (float)(unsigned int)(c & 0xFFFFFFFFull) * inv_n;
            float p1 = (float)(unsigned int)(c >> 32) * inv_n;
            v += p0 * logf(p0 + 1e-8f);
            v += p1 * logf(p1 + 1e-8f);
        }
        #pragma unroll
        for (int o = 16; o > 0; o >>= 1) v += __shfl_down_sync(0xFFFFFFFFu, v, o);
        if ((t & 31) == 0) red[t >> 5] = v;
        __syncthreads();
        if (t < 32) {
            float s = (t < HIST_THREADS / 32) ? red[t] : 0.0f;
            #pragma unroll
            for (int o = 4; o > 0; o >>= 1) s += __shfl_down_sync(0xFFFFFFFFu, s, o);
            if (t == 0) {
                out[0] = expf(-s);
                g_done = 0u;                  // reset arrival counter for next replay
            }
        }
    }
}

extern "C" void kernel_launch(void* const* d_in, const int* in_sizes, int n_in,
                              void* d_out, int out_size) {
    const int* idx = (const int*)d_in[0];
    long long n    = (long long)in_sizes[0];
    float* out     = (float*)d_out;

    hist_kernel<<<HIST_BLOCKS, HIST_THREADS>>>(idx, n, 1.0f / (float)n, out);
}

// round 11
// speedup vs baseline: 1.1196x; 1.1196x over previous
#include <cuda_runtime.h>
#include <math.h>

#define N_BINS 1024
#define N_COPIES 8           // one PRIVATE smem histogram per warp (256 thr / 32)
#define HIST_BLOCKS 592      // 4 * 148 SMs (R3 config)
#define HIST_THREADS 256
#define N_REP 4              // global histogram replicas: 4096 atomic targets

__device__ unsigned int g_rep[N_REP][N_BINS];  // zero at load; reset each run below
__device__ unsigned int g_done;                // arrival counter, reset each run

__global__ void __launch_bounds__(HIST_THREADS) hist_kernel(
    const int* __restrict__ idx, long long n, float inv_n,
    float* __restrict__ out)
{
    __shared__ __align__(16) unsigned int sh[N_COPIES][N_BINS];
    __shared__ bool s_last;
    __shared__ float red[HIST_THREADS / 32];

    unsigned int* flat = &sh[0][0];
    for (int i = threadIdx.x; i < N_COPIES * N_BINS; i += blockDim.x)
        flat[i] = 0u;
    __syncthreads();

    unsigned int* h = sh[threadIdx.x >> 5];   // fully private per-warp copy

    long long tid    = (long long)blockIdx.x * blockDim.x + threadIdx.x;
    long long stride = (long long)gridDim.x * blockDim.x;
    long long n4     = n >> 2;
    const int4* p4   = (const int4*)idx;

    // main loop: 2 outstanding int4 loads per iteration (R3's exact body)
    long long i = tid;
    for (; i + stride < n4; i += 2 * stride) {
        int4 a = p4[i];
        int4 b = p4[i + stride];
        atomicAdd(&h[a.x & (N_BINS - 1)], 1u);
        atomicAdd(&h[a.y & (N_BINS - 1)], 1u);
        atomicAdd(&h[a.z & (N_BINS - 1)], 1u);
        atomicAdd(&h[a.w & (N_BINS - 1)], 1u);
        atomicAdd(&h[b.x & (N_BINS - 1)], 1u);
        atomicAdd(&h[b.y & (N_BINS - 1)], 1u);
        atomicAdd(&h[b.z & (N_BINS - 1)], 1u);
        atomicAdd(&h[b.w & (N_BINS - 1)], 1u);
    }
    for (; i < n4; i += stride) {
        int4 a = p4[i];
        atomicAdd(&h[a.x & (N_BINS - 1)], 1u);
        atomicAdd(&h[a.y & (N_BINS - 1)], 1u);
        atomicAdd(&h[a.z & (N_BINS - 1)], 1u);
        atomicAdd(&h[a.w & (N_BINS - 1)], 1u);
    }
    // remainder (n not multiple of 4)
    for (long long r = (n4 << 2) + tid; r < n; r += stride)
        atomicAdd(&h[idx[r] & (N_BINS - 1)], 1u);

    __syncthreads();

    // flush: per-warp copies -> one of 4 replica histograms (blockIdx & 3).
    // 4096 distinct atomic targets, only 148 ops per address -> 4x less
    // per-address serialization at the LTS atomic ALUs than a single histogram.
    unsigned int* grow = g_rep[blockIdx.x & (N_REP - 1)];
    for (int b = threadIdx.x; b < N_BINS; b += blockDim.x) {
        unsigned int s = 0;
        #pragma unroll
        for (int c = 0; c < N_COPIES; c++) s += sh[c][b];
        atomicAdd(&grow[b], s);
    }

    // last-block-done: fused finalize
    __threadfence();
    if (threadIdx.x == 0)
        s_last = (atomicAdd(&g_done, 1u) == (unsigned)(gridDim.x - 1));
    __syncthreads();

    if (s_last) {
        int t = threadIdx.x;
        volatile unsigned int* gc = &g_rep[0][0];
        float v = 0.0f;
        #pragma unroll
        for (int k = 0; k < N_BINS / HIST_THREADS; k++) {
            int b = t + k * HIST_THREADS;
            unsigned int c = 0;
            #pragma unroll
            for (int r = 0; r < N_REP; r++) {
                c += gc[r * N_BINS + b];
                g_rep[r][b] = 0u;             // reset for next replay
            }
            float p = (float)c * inv_n;
            v += p * logf(p + 1e-8f);
        }
        #pragma unroll
        for (int o = 16; o > 0; o >>= 1) v += __shfl_down_sync(0xFFFFFFFFu, v, o);
        if ((t & 31) == 0) red[t >> 5] = v;
        __syncthreads();
        if (t < 32) {
            float s = (t < HIST_THREADS / 32) ? red[t] : 0.0f;
            #pragma unroll
            for (int o = 4; o > 0; o >>= 1) s += __shfl_down_sync(0xFFFFFFFFu, s, o);
            if (t == 0) {
                out[0] = expf(-s);
                g_done = 0u;                  // reset arrival counter for next replay
            }
        }
    }
}

extern "C" void kernel_launch(void* const* d_in, const int* in_sizes, int n_in,
                              void* d_out, int out_size) {
    const int* idx = (const int*)d_in[0];
    long long n    = (long long)in_sizes[0];
    float* out     = (float*)d_out;

    hist_kernel<<<HIST_BLOCKS, HIST_THREADS>>>(idx, n, 1.0f / (float)n, out);
}